// round 13
// baseline (speedup 1.0000x reference)
#include <cuda_runtime.h>
#include <cuda_bf16.h>
#include <math.h>
#include <stdint.h>

// ---------------- problem constants ----------------
#define BB   8
#define HH   32
#define WW   32
#define DIM  768
#define NH   6
#define NP   4
#define DV   384
#define DH   64
#define HID  192
#define LQ   5376
#define LIN  1024
#define NTOK (BB*LQ)    // 43008
#define NCHUNK 4
#define NQUAR (NTOK/NCHUNK)  // 10752 (= 2 batches each)
#define NFEAT (BB*LIN)  // 8192
#define OA_LD 96        // padded projection width

// ---------------- scratch (device globals) ----------------
__device__ __nv_bfloat16 g_v[NFEAT * DV];
__device__ float g_oa[NTOK * OA_LD];
__device__ __nv_bfloat16 g_h1b[NTOK * HID];
__device__ __nv_bfloat16 g_lnq[NTOK * DIM];
__device__ __nv_bfloat16 g_lnf[NFEAT * DIM];
__device__ __nv_bfloat16 g_lnx[NTOK * DIM];
__device__ __nv_bfloat16 g_attnb[NTOK * DV];
__device__ __nv_bfloat16 g_h2b[NTOK * HID];
__device__ __nv_bfloat16 g_wval[DV * DIM];
__device__ __nv_bfloat16 g_wout[DIM * DV];
__device__ __nv_bfloat16 g_wproj[OA_LD * DIM];
__device__ __nv_bfloat16 g_wfc1[HID * DIM];
__device__ __nv_bfloat16 g_wfc2[DIM * HID];
__device__ float g_bproj[OA_LD];

// ---------------- static streams/events for graph fork ----------------
struct StreamInit {
    cudaStream_t st[3];   // chunk streams 1..3 (chunk 0 on default)
    cudaStream_t sv;      // v-GEMM stream
    cudaEvent_t e0, ev;
    cudaEvent_t ej[3];
    StreamInit() {
        for (int i = 0; i < 3; i++)
            cudaStreamCreateWithFlags(&st[i], cudaStreamNonBlocking);
        cudaStreamCreateWithFlags(&sv, cudaStreamNonBlocking);
        cudaEventCreateWithFlags(&e0, cudaEventDisableTiming);
        cudaEventCreateWithFlags(&ev, cudaEventDisableTiming);
        for (int i = 0; i < 3; i++)
            cudaEventCreateWithFlags(&ej[i], cudaEventDisableTiming);
    }
};
static StreamInit g_si;

// ---------------- PTX helpers (sm_80+ portable) ----------------
__device__ __forceinline__ uint32_t smem_u32(const void* p) {
    uint32_t a;
    asm("{ .reg .u64 t; cvta.to.shared.u64 t, %1; cvt.u32.u64 %0, t; }" : "=r"(a) : "l"(p));
    return a;
}
__device__ __forceinline__ void cp16(uint32_t s, const void* g) {
    asm volatile("cp.async.cg.shared.global [%0], [%1], 16;" :: "r"(s), "l"(g));
}
#define CP_COMMIT() asm volatile("cp.async.commit_group;" ::: "memory")
#define CP_WAIT(n)  asm volatile("cp.async.wait_group %0;" :: "n"(n) : "memory")

__device__ __forceinline__ void ldmx4(uint32_t* r, uint32_t addr) {
    asm volatile("ldmatrix.sync.aligned.m8n8.x4.shared.b16 {%0,%1,%2,%3}, [%4];"
        : "=r"(r[0]), "=r"(r[1]), "=r"(r[2]), "=r"(r[3]) : "r"(addr));
}
__device__ __forceinline__ void mma16816(float* c, const uint32_t* a, const uint32_t* b) {
    asm volatile(
        "mma.sync.aligned.m16n8k16.row.col.f32.bf16.bf16.f32 "
        "{%0,%1,%2,%3}, {%4,%5,%6,%7}, {%8,%9}, {%0,%1,%2,%3};"
        : "+f"(c[0]), "+f"(c[1]), "+f"(c[2]), "+f"(c[3])
        : "r"(a[0]), "r"(a[1]), "r"(a[2]), "r"(a[3]), "r"(b[0]), "r"(b[1]));
}

// ---------------- warp-per-row LayerNorm + bf16 cast (no barriers) -------
__global__ __launch_bounds__(256) void ln_cast_w(const float* __restrict__ X,
                                                 const float* __restrict__ g,
                                                 const float* __restrict__ bta,
                                                 __nv_bfloat16* __restrict__ Y)
{
    const int warp = threadIdx.x >> 5, lane = threadIdx.x & 31;
    const int row = blockIdx.x * 8 + warp;
    const float* x = X + (size_t)row * DIM;

    float4 v[6];
    #pragma unroll
    for (int k = 0; k < 6; k++)
        v[k] = *(const float4*)(x + k * 128 + lane * 4);

    float s = 0.f, q = 0.f;
    #pragma unroll
    for (int k = 0; k < 6; k++) {
        s += v[k].x + v[k].y + v[k].z + v[k].w;
        q += v[k].x * v[k].x + v[k].y * v[k].y + v[k].z * v[k].z + v[k].w * v[k].w;
    }
    #pragma unroll
    for (int o = 16; o > 0; o >>= 1) {
        s += __shfl_xor_sync(0xffffffffu, s, o);
        q += __shfl_xor_sync(0xffffffffu, q, o);
    }
    const float m = s * (1.f / DIM);
    const float r = rsqrtf(q * (1.f / DIM) - m * m + 1e-6f);

    __nv_bfloat16* y = Y + (size_t)row * DIM;
    #pragma unroll
    for (int k = 0; k < 6; k++) {
        const int i = k * 128 + lane * 4;
        float4 g4 = *(const float4*)(g + i);
        float4 b4 = *(const float4*)(bta + i);
        float o0 = (v[k].x - m) * r * g4.x + b4.x;
        float o1 = (v[k].y - m) * r * g4.y + b4.y;
        float o2 = (v[k].z - m) * r * g4.z + b4.z;
        float o3 = (v[k].w - m) * r * g4.w + b4.w;
        __nv_bfloat162 h0, h1;
        h0.x = __float2bfloat16(o0); h0.y = __float2bfloat16(o1);
        h1.x = __float2bfloat16(o2); h1.y = __float2bfloat16(o3);
        uint2 pk;
        pk.x = *(uint32_t*)&h0; pk.y = *(uint32_t*)&h1;
        *(uint2*)(y + i) = pk;
    }
}

// ---------------- one-shot weight prep ----------------
#define SEG0 (DIM*DV)
#define SEG1 (DV*DIM)
#define SEG2 (DIM*HID)
#define SEG3 (HID*DIM)
#define SEG4 (OA_LD*DIM)
#define PREP_TOT (SEG0+SEG1+SEG2+SEG3+SEG4+OA_LD)
__global__ __launch_bounds__(256) void prep_weights(
    const float* __restrict__ W_val, const float* __restrict__ W_out,
    const float* __restrict__ fc1_w, const float* __restrict__ fc2_w,
    const float* __restrict__ Woff, const float* __restrict__ Wattn,
    const float* __restrict__ boff, const float* __restrict__ battn,
    __nv_bfloat16* __restrict__ wval, __nv_bfloat16* __restrict__ wout,
    __nv_bfloat16* __restrict__ wfc1, __nv_bfloat16* __restrict__ wfc2,
    __nv_bfloat16* __restrict__ wproj, float* __restrict__ bproj)
{
    int gid = blockIdx.x * 256 + threadIdx.x;
    if (gid < SEG0) {
        int k = gid / DV, n = gid % DV;
        wval[(size_t)n * DIM + k] = __float2bfloat16(W_val[gid]);
        return;
    }
    gid -= SEG0;
    if (gid < SEG1) {
        int k = gid / DIM, n = gid % DIM;
        wout[(size_t)n * DV + k] = __float2bfloat16(W_out[gid]);
        return;
    }
    gid -= SEG1;
    if (gid < SEG2) {
        int k = gid / HID, n = gid % HID;
        wfc1[(size_t)n * DIM + k] = __float2bfloat16(fc1_w[gid]);
        return;
    }
    gid -= SEG2;
    if (gid < SEG3) {
        int k = gid / DIM, n = gid % DIM;
        wfc2[(size_t)n * HID + k] = __float2bfloat16(fc2_w[gid]);
        return;
    }
    gid -= SEG3;
    if (gid < SEG4) {
        int n = gid / DIM, k = gid % DIM;
        float v = 0.f;
        if (n < 48)      v = Woff[(size_t)k * 48 + n];
        else if (n < 72) v = Wattn[(size_t)k * 24 + (n - 48)];
        wproj[gid] = __float2bfloat16(v);
        return;
    }
    gid -= SEG4;
    if (gid < OA_LD)
        bproj[gid] = (gid < 48) ? boff[gid] : ((gid < 72) ? battn[gid - 48] : 0.f);
}

// ---------------- bf16 mma.sync GEMM: BK=32, 3-stage cp.async -----------
// (R4-measured fastest mainloop: CP_WAIT(1), one __syncthreads per chunk)
#define BM 128
#define BN 96
#define APAD 40
#define STAGES 3
#define STG ((BM + BN) * APAD)
#define GEMM_SMEM (STAGES * STG * 2)

template<bool RES, bool ACC, bool OUTBF>
__global__ __launch_bounds__(256) void gemm_mma(
    const __nv_bfloat16* __restrict__ A,   // [M,K] row-major
    const __nv_bfloat16* __restrict__ Bt,  // [N,K] row-major
    const float* __restrict__ bias,        // [N]
    const float* __restrict__ R,           // [M,N] residual (RES)
    void* __restrict__ Cv, int M, int N, int K)
{
    extern __shared__ __nv_bfloat16 dsm[];

    const int tid  = threadIdx.x;
    const int wid  = tid >> 5, lane = tid & 31;
    const int wm   = wid >> 1, wn = wid & 1;
    const int bm   = blockIdx.y * BM, bn = blockIdx.x * BN;

    float acc[2][6][4];
    #pragma unroll
    for (int i = 0; i < 2; i++)
        #pragma unroll
        for (int j = 0; j < 6; j++)
            #pragma unroll
            for (int v = 0; v < 4; v++) acc[i][j][v] = 0.f;

    const uint32_t uS = smem_u32(dsm);
    const int ar0 = tid >> 2, ac0 = (tid & 3) * 8;
    const int ar1 = ar0 + 64;
    const int br0 = tid >> 2;
    const int br1 = br0 + 64;

    const int a_r = wm * 32 + (lane & 15);
    const int a_c = (lane >> 4) * 8;
    const int b_r = wn * 48 + ((lane >> 4) & 1) * 8 + (lane & 7);
    const int b_c = ((lane >> 3) & 1) * 8;

    const int nk = K >> 5;

    // ---- prologue: stages 0..STAGES-2 ----
    #pragma unroll
    for (int s = 0; s < STAGES - 1; s++) {
        const int k0 = s << 5;
        const uint32_t baseA = uS + (uint32_t)(s * STG) * 2;
        const uint32_t baseB = baseA + (uint32_t)(BM * APAD) * 2;
        cp16(baseA + (uint32_t)(ar0 * APAD + ac0) * 2, A  + (size_t)(bm + ar0) * K + k0 + ac0);
        cp16(baseA + (uint32_t)(ar1 * APAD + ac0) * 2, A  + (size_t)(bm + ar1) * K + k0 + ac0);
        cp16(baseB + (uint32_t)(br0 * APAD + ac0) * 2, Bt + (size_t)(bn + br0) * K + k0 + ac0);
        if (tid < 128)
            cp16(baseB + (uint32_t)(br1 * APAD + ac0) * 2, Bt + (size_t)(bn + br1) * K + k0 + ac0);
        CP_COMMIT();
    }

    for (int c = 0; c < nk; c++) {
        CP_WAIT(STAGES - 2);
        __syncthreads();

        // issue stage c+STAGES-1 into buffer (c+STAGES-1)%STAGES
        {
            const int s = c + STAGES - 1;
            if (s < nk) {
                const int k0 = s << 5;
                const int sb = s % STAGES;
                const uint32_t baseA = uS + (uint32_t)(sb * STG) * 2;
                const uint32_t baseB = baseA + (uint32_t)(BM * APAD) * 2;
                cp16(baseA + (uint32_t)(ar0 * APAD + ac0) * 2,
                     A + (size_t)(bm + ar0) * K + k0 + ac0);
                cp16(baseA + (uint32_t)(ar1 * APAD + ac0) * 2,
                     A + (size_t)(bm + ar1) * K + k0 + ac0);
                cp16(baseB + (uint32_t)(br0 * APAD + ac0) * 2,
                     Bt + (size_t)(bn + br0) * K + k0 + ac0);
                if (tid < 128)
                    cp16(baseB + (uint32_t)(br1 * APAD + ac0) * 2,
                         Bt + (size_t)(bn + br1) * K + k0 + ac0);
            }
            CP_COMMIT();
        }

        // ---- compute stage c ----
        const int sb = c % STAGES;
        const uint32_t bA = uS + (uint32_t)(sb * STG) * 2;
        const uint32_t bB = bA + (uint32_t)(BM * APAD) * 2;
        #pragma unroll
        for (int kk = 0; kk < 2; kk++) {
            uint32_t afr[2][4];
            #pragma unroll
            for (int mt = 0; mt < 2; mt++)
                ldmx4(afr[mt], bA + (uint32_t)((a_r + mt * 16) * APAD + kk * 16 + a_c) * 2);
            uint32_t bfr[6][2];
            #pragma unroll
            for (int g = 0; g < 3; g++) {
                uint32_t r[4];
                ldmx4(r, bB + (uint32_t)((b_r + g * 16) * APAD + kk * 16 + b_c) * 2);
                bfr[g * 2 + 0][0] = r[0]; bfr[g * 2 + 0][1] = r[1];
                bfr[g * 2 + 1][0] = r[2]; bfr[g * 2 + 1][1] = r[3];
            }
            #pragma unroll
            for (int mt = 0; mt < 2; mt++)
                #pragma unroll
                for (int nt = 0; nt < 6; nt++)
                    mma16816(acc[mt][nt], afr[mt], bfr[nt]);
        }
    }

    // ---- epilogue ----
    const int er = bm + wm * 32 + (lane >> 2);
    const int ec = bn + wn * 48 + (lane & 3) * 2;
    #pragma unroll
    for (int mt = 0; mt < 2; mt++) {
        #pragma unroll
        for (int nt = 0; nt < 6; nt++) {
            const int row0 = er + mt * 16;
            const int col  = ec + nt * 8;
            float2 bv = *(const float2*)&bias[col];
            size_t off0 = (size_t)row0 * N + col;
            size_t off1 = off0 + (size_t)8 * N;
            float2 o0, o1;
            o0.x = acc[mt][nt][0] + bv.x; o0.y = acc[mt][nt][1] + bv.y;
            o1.x = acc[mt][nt][2] + bv.x; o1.y = acc[mt][nt][3] + bv.y;
            if (OUTBF) {
                __nv_bfloat16* Cb = (__nv_bfloat16*)Cv;
                __nv_bfloat162 h0, h1;
                h0.x = __float2bfloat16(o0.x); h0.y = __float2bfloat16(o0.y);
                h1.x = __float2bfloat16(o1.x); h1.y = __float2bfloat16(o1.y);
                *(__nv_bfloat162*)&Cb[off0] = h0;
                *(__nv_bfloat162*)&Cb[off1] = h1;
            } else {
                float* C = (float*)Cv;
                if (RES) {
                    float2 r0 = *(const float2*)&R[off0];
                    float2 r1 = *(const float2*)&R[off1];
                    o0.x += r0.x; o0.y += r0.y; o1.x += r1.x; o1.y += r1.y;
                }
                if (ACC) {
                    float2 c0 = *(const float2*)&C[off0];
                    float2 c1 = *(const float2*)&C[off1];
                    o0.x += c0.x; o0.y += c0.y; o1.x += c1.x; o1.y += c1.y;
                }
                *(float2*)&C[off0] = o0;
                *(float2*)&C[off1] = o1;
            }
        }
    }
}

// ---------------- sampling: warp-per-token, 8 tokens per block ----------
__global__ __launch_bounds__(256) void sample_kernel(
    const float* __restrict__ oa,       // [NTOK, 96]  (absolute)
    const float* __restrict__ refp,
    __nv_bfloat16* __restrict__ attn_bf,
    int t0)
{
    __shared__ int   sidx[8][96];
    __shared__ float swt[8][96];

    const int wid = threadIdx.x >> 5, lane = threadIdx.x & 31;
    const int t = t0 + blockIdx.x * 8 + wid;
    const float* oarow = oa + (size_t)t * OA_LD;

    if (lane < 24) {
        const int h = lane >> 2, p = lane & 3;
        float l0 = oarow[48 + h * 4 + 0], l1 = oarow[48 + h * 4 + 1];
        float l2 = oarow[48 + h * 4 + 2], l3 = oarow[48 + h * 4 + 3];
        float mx = fmaxf(fmaxf(l0, l1), fmaxf(l2, l3));
        float e0 = expf(l0 - mx), e1 = expf(l1 - mx);
        float e2 = expf(l2 - mx), e3 = expf(l3 - mx);
        float inv = 1.f / (e0 + e1 + e2 + e3);
        float ep = (p == 0) ? e0 : (p == 1) ? e1 : (p == 2) ? e2 : e3;
        const float a = ep * inv;

        float rx = refp[(size_t)t * 2 + 0];
        float ry = refp[(size_t)t * 2 + 1];
        float lx = rx + oarow[h * 8 + p * 2 + 0] * (1.f / (float)WW);
        float ly = ry + oarow[h * 8 + p * 2 + 1] * (1.f / (float)HH);
        float x = lx * (float)WW - 0.5f;
        float y = ly * (float)HH - 0.5f;
        float x0f = floorf(x), y0f = floorf(y);
        float wx = x - x0f, wy = y - y0f;
        int x0 = (int)x0f, y0 = (int)y0f;
        #pragma unroll
        for (int c = 0; c < 4; c++) {
            int dx = c & 1, dy = c >> 1;
            int xi = x0 + dx, yi = y0 + dy;
            bool ok = (xi >= 0) && (xi < WW) && (yi >= 0) && (yi < HH);
            sidx[wid][lane * 4 + c] = ok ? (yi * WW + xi) : -1;
            float wgt = (dx ? wx : 1.f - wx) * (dy ? wy : 1.f - wy);
            swt[wid][lane * 4 + c] = ok ? wgt * a : 0.f;
        }
    }
    __syncwarp();

    const __nv_bfloat16* vb = g_v + (size_t)(t / LQ) * LIN * DV;
    #pragma unroll
    for (int j = 0; j < 6; j++) {            // head == j for this lane's dims
        const int d = j * 64 + lane * 2;
        float ax = 0.f, ay = 0.f;
        #pragma unroll
        for (int p = 0; p < 4; p++) {
            const int hp = j * 4 + p;
            #pragma unroll
            for (int c = 0; c < 4; c++) {
                int idx = sidx[wid][hp * 4 + c];
                float wv = swt[wid][hp * 4 + c];
                if (idx >= 0) {
                    __nv_bfloat162 v = *(const __nv_bfloat162*)&vb[(size_t)idx * DV + d];
                    ax += wv * __bfloat162float(v.x);
                    ay += wv * __bfloat162float(v.y);
                }
            }
        }
        __nv_bfloat162 o;
        o.x = __float2bfloat16(ax); o.y = __float2bfloat16(ay);
        *(__nv_bfloat162*)&attn_bf[(size_t)t * DV + d] = o;
    }
}

// ---------------- depthwise 3x3 conv (bf16 in) + GELU, 4 outs/thread ----
__global__ __launch_bounds__(256) void dwconv_gelu(
    const __nv_bfloat16* __restrict__ hin, const float* __restrict__ dww,
    const float* __restrict__ dwb, __nv_bfloat16* __restrict__ hout,
    int gid0)
{
    const int base = gid0 + blockIdx.x * 1024 + threadIdx.x;
    #pragma unroll
    for (int it = 0; it < 4; it++) {
        const int gid = base + it * 256;
        int ch = gid % HID;
        int t  = (gid / HID) % LQ;
        int b  = gid / (HID * LQ);

        int lvbase, hh, ww;
        if (t < 4096)      { lvbase = 0;    hh = 64; ww = 64; }
        else if (t < 5120) { lvbase = 4096; hh = 32; ww = 32; }
        else               { lvbase = 5120; hh = 16; ww = 16; }
        int tl = t - lvbase;
        int rr = tl / ww, cc = tl % ww;

        const __nv_bfloat16* in = hin + ((size_t)b * LQ + lvbase) * HID + ch;
        float acc = dwb[ch];
        #pragma unroll
        for (int ky = 0; ky < 3; ky++) {
            int y = rr + ky - 1;
            if (y < 0 || y >= hh) continue;
            #pragma unroll
            for (int kx = 0; kx < 3; kx++) {
                int x = cc + kx - 1;
                if (x < 0 || x >= ww) continue;
                acc += __bfloat162float(in[(size_t)(y * ww + x) * HID])
                     * dww[(ky * 3 + kx) * HID + ch];
            }
        }
        float ge = 0.5f * acc * (1.f + erff(acc * 0.70710678118654752440f));
        hout[gid] = __float2bfloat16(ge);
    }
}

// ---------------- host launcher ----------------
extern "C" void kernel_launch(void* const* d_in, const int* in_sizes, int n_in,
                              void* d_out, int out_size)
{
    const float* query  = (const float*)d_in[0];
    const float* refp   = (const float*)d_in[1];
    const float* feat   = (const float*)d_in[2];
    const float* qn_g   = (const float*)d_in[5];
    const float* qn_b   = (const float*)d_in[6];
    const float* fn_g   = (const float*)d_in[7];
    const float* fn_b   = (const float*)d_in[8];
    const float* W_off  = (const float*)d_in[9];
    const float* b_off  = (const float*)d_in[10];
    const float* W_attn = (const float*)d_in[11];
    const float* b_attn = (const float*)d_in[12];
    const float* W_val  = (const float*)d_in[13];
    const float* b_val  = (const float*)d_in[14];
    const float* W_out  = (const float*)d_in[15];
    const float* b_out  = (const float*)d_in[16];
    const float* ffn_g  = (const float*)d_in[17];
    const float* ffn_b  = (const float*)d_in[18];
    const float* fc1_w  = (const float*)d_in[19];
    const float* fc1_b  = (const float*)d_in[20];
    const float* dw_w   = (const float*)d_in[21];
    const float* dw_b   = (const float*)d_in[22];
    const float* fc2_w  = (const float*)d_in[23];
    const float* fc2_b  = (const float*)d_in[24];
    float* out = (float*)d_out;

    float *poa, *pbproj;
    __nv_bfloat16 *pv, *ph1b, *plnq, *plnf, *plnx, *pattnb, *ph2b;
    __nv_bfloat16 *pwval, *pwout, *pwproj, *pwfc1, *pwfc2;
    cudaGetSymbolAddress((void**)&pv,     g_v);
    cudaGetSymbolAddress((void**)&poa,    g_oa);
    cudaGetSymbolAddress((void**)&ph1b,   g_h1b);
    cudaGetSymbolAddress((void**)&pbproj, g_bproj);
    cudaGetSymbolAddress((void**)&plnq,   g_lnq);
    cudaGetSymbolAddress((void**)&plnf,   g_lnf);
    cudaGetSymbolAddress((void**)&plnx,   g_lnx);
    cudaGetSymbolAddress((void**)&pattnb, g_attnb);
    cudaGetSymbolAddress((void**)&ph2b,   g_h2b);
    cudaGetSymbolAddress((void**)&pwval,  g_wval);
    cudaGetSymbolAddress((void**)&pwout,  g_wout);
    cudaGetSymbolAddress((void**)&pwproj, g_wproj);
    cudaGetSymbolAddress((void**)&pwfc1,  g_wfc1);
    cudaGetSymbolAddress((void**)&pwfc2,  g_wfc2);

    cudaFuncSetAttribute(gemm_mma<false,false,true>,
        cudaFuncAttributeMaxDynamicSharedMemorySize, GEMM_SMEM);
    cudaFuncSetAttribute(gemm_mma<false,false,false>,
        cudaFuncAttributeMaxDynamicSharedMemorySize, GEMM_SMEM);
    cudaFuncSetAttribute(gemm_mma<true,false,false>,
        cudaFuncAttributeMaxDynamicSharedMemorySize, GEMM_SMEM);
    cudaFuncSetAttribute(gemm_mma<false,true,false>,
        cudaFuncAttributeMaxDynamicSharedMemorySize, GEMM_SMEM);

    const int GM = NQUAR / BM;     // 84 row-tiles per chunk
    cudaStream_t cs[NCHUNK] = {0, g_si.st[0], g_si.st[1], g_si.st[2]};

    // ---- main: weight prep (gates proj + v GEMMs) ----
    prep_weights<<<(PREP_TOT + 255) / 256, 256>>>(
        W_val, W_out, fc1_w, fc2_w, W_off, W_attn, b_off, b_attn,
        pwval, pwout, pwfc1, pwfc2, pwproj, pbproj);
    cudaEventRecord(g_si.e0, 0);

    // ---- sv: feat LN -> v GEMM ----
    ln_cast_w<<<NFEAT / 8, 256, 0, g_si.sv>>>(feat, fn_g, fn_b, plnf);
    cudaStreamWaitEvent(g_si.sv, g_si.e0, 0);
    gemm_mma<false, false, true><<<dim3(DV / BN, NFEAT / BM), 256, GEMM_SMEM, g_si.sv>>>(
        plnf, pwval, b_val, nullptr, pv, NFEAT, DV, DIM);
    cudaEventRecord(g_si.ev, g_si.sv);

    // ---- per-chunk pipelines (chunk c on stream cs[c]) ----
    // stage 1: ln_q
    for (int c = 0; c < NCHUNK; c++) {
        const size_t off = (size_t)c * NQUAR;
        ln_cast_w<<<NQUAR / 8, 256, 0, cs[c]>>>(
            query + off * DIM, qn_g, qn_b, plnq + off * DIM);
        if (c > 0) cudaStreamWaitEvent(cs[c], g_si.e0, 0);
    }
    // stage 2: proj GEMM
    for (int c = 0; c < NCHUNK; c++) {
        const size_t off = (size_t)c * NQUAR;
        gemm_mma<false, false, false><<<dim3(1, GM), 256, GEMM_SMEM, cs[c]>>>(
            plnq + off * DIM, pwproj, pbproj, nullptr,
            poa + off * OA_LD, NQUAR, OA_LD, DIM);
    }
    // stage 3: sample (needs v)
    for (int c = 0; c < NCHUNK; c++) {
        cudaStreamWaitEvent(cs[c], g_si.ev, 0);
        sample_kernel<<<NQUAR / 8, 256, 0, cs[c]>>>(poa, refp, pattnb,
                                                    c * NQUAR);
    }
    // stage 4: W_out GEMM (+query residual)
    for (int c = 0; c < NCHUNK; c++) {
        const size_t off = (size_t)c * NQUAR;
        gemm_mma<true, false, false><<<dim3(DIM / BN, GM), 256, GEMM_SMEM, cs[c]>>>(
            pattnb + off * DV, pwout, b_out, query + off * DIM,
            out + off * DIM, NQUAR, DIM, DV);
    }
    // stage 5: LN(x)
    for (int c = 0; c < NCHUNK; c++) {
        const size_t off = (size_t)c * NQUAR;
        ln_cast_w<<<NQUAR / 8, 256, 0, cs[c]>>>(
            out + off * DIM, ffn_g, ffn_b, plnx + off * DIM);
    }
    // stage 6: fc1
    for (int c = 0; c < NCHUNK; c++) {
        const size_t off = (size_t)c * NQUAR;
        gemm_mma<false, false, true><<<dim3(HID / BN, GM), 256, GEMM_SMEM, cs[c]>>>(
            plnx + off * DIM, pwfc1, fc1_b, nullptr,
            ph1b + off * HID, NQUAR, HID, DIM);
    }
    // stage 7: dwconv + gelu
    for (int c = 0; c < NCHUNK; c++) {
        dwconv_gelu<<<(NQUAR * HID) / 1024, 256, 0, cs[c]>>>(
            ph1b, dw_w, dw_b, ph2b, c * NQUAR * HID);
    }
    // stage 8: fc2 (+= into out)
    for (int c = 0; c < NCHUNK; c++) {
        const size_t off = (size_t)c * NQUAR;
        gemm_mma<false, true, false><<<dim3(DIM / BN, GM), 256, GEMM_SMEM, cs[c]>>>(
            ph2b + off * HID, pwfc2, fc2_b, nullptr,
            out + off * DIM, NQUAR, DIM, HID);
    }

    // join: default stream waits for chunks 1..3
    for (int c = 1; c < NCHUNK; c++) {
        cudaEventRecord(g_si.ej[c - 1], cs[c]);
        cudaStreamWaitEvent(0, g_si.ej[c - 1], 0);
    }
}

// round 14
// speedup vs baseline: 1.0727x; 1.0727x over previous
#include <cuda_runtime.h>
#include <cuda_bf16.h>
#include <math.h>
#include <stdint.h>

// ---------------- problem constants ----------------
#define BB   8
#define HH   32
#define WW   32
#define DIM  768
#define NH   6
#define NP   4
#define DV   384
#define DH   64
#define HID  192
#define LQ   5376
#define LIN  1024
#define NTOK (BB*LQ)    // 43008
#define NCHUNK 4
#define NQUAR (NTOK/NCHUNK)  // 10752 (= 2 batches each)
#define NFEAT (BB*LIN)  // 8192
#define OA_LD 96        // padded projection width

// ---------------- scratch (device globals) ----------------
__device__ __nv_bfloat16 g_v[NFEAT * DV];
__device__ float g_oa[NTOK * OA_LD];
__device__ __nv_bfloat16 g_h1b[NTOK * HID];
__device__ __nv_bfloat16 g_lnq[NTOK * DIM];
__device__ __nv_bfloat16 g_lnf[NFEAT * DIM];
__device__ __nv_bfloat16 g_lnx[NTOK * DIM];
__device__ __nv_bfloat16 g_attnb[NTOK * DV];
__device__ __nv_bfloat16 g_h2b[NTOK * HID];
__device__ __nv_bfloat16 g_wval[DV * DIM];
__device__ __nv_bfloat16 g_wout[DIM * DV];
__device__ __nv_bfloat16 g_wproj[OA_LD * DIM];
__device__ __nv_bfloat16 g_wfc1[HID * DIM];
__device__ __nv_bfloat16 g_wfc2[DIM * HID];
__device__ float g_bproj[OA_LD];

// ---------------- static streams/events for graph fork ----------------
struct StreamInit {
    cudaStream_t st[3];   // chunk streams 1..3 (chunk 0 on default)
    cudaStream_t sv;      // v-GEMM stream
    cudaEvent_t e0, ev;
    cudaEvent_t ej[3];
    StreamInit() {
        for (int i = 0; i < 3; i++)
            cudaStreamCreateWithFlags(&st[i], cudaStreamNonBlocking);
        cudaStreamCreateWithFlags(&sv, cudaStreamNonBlocking);
        cudaEventCreateWithFlags(&e0, cudaEventDisableTiming);
        cudaEventCreateWithFlags(&ev, cudaEventDisableTiming);
        for (int i = 0; i < 3; i++)
            cudaEventCreateWithFlags(&ej[i], cudaEventDisableTiming);
    }
};
static StreamInit g_si;

// ---------------- PTX helpers (sm_80+ portable) ----------------
__device__ __forceinline__ uint32_t smem_u32(const void* p) {
    uint32_t a;
    asm("{ .reg .u64 t; cvta.to.shared.u64 t, %1; cvt.u32.u64 %0, t; }" : "=r"(a) : "l"(p));
    return a;
}
__device__ __forceinline__ void cp16(uint32_t s, const void* g) {
    asm volatile("cp.async.cg.shared.global [%0], [%1], 16;" :: "r"(s), "l"(g));
}
#define CP_COMMIT() asm volatile("cp.async.commit_group;" ::: "memory")
#define CP_WAIT(n)  asm volatile("cp.async.wait_group %0;" :: "n"(n) : "memory")

__device__ __forceinline__ void ldmx4(uint32_t* r, uint32_t addr) {
    asm volatile("ldmatrix.sync.aligned.m8n8.x4.shared.b16 {%0,%1,%2,%3}, [%4];"
        : "=r"(r[0]), "=r"(r[1]), "=r"(r[2]), "=r"(r[3]) : "r"(addr));
}
__device__ __forceinline__ void mma16816(float* c, const uint32_t* a, const uint32_t* b) {
    asm volatile(
        "mma.sync.aligned.m16n8k16.row.col.f32.bf16.bf16.f32 "
        "{%0,%1,%2,%3}, {%4,%5,%6,%7}, {%8,%9}, {%0,%1,%2,%3};"
        : "+f"(c[0]), "+f"(c[1]), "+f"(c[2]), "+f"(c[3])
        : "r"(a[0]), "r"(a[1]), "r"(a[2]), "r"(a[3]), "r"(b[0]), "r"(b[1]));
}

// ---------------- warp-per-row LayerNorm + bf16 cast (no barriers) -------
__global__ __launch_bounds__(256) void ln_cast_w(const float* __restrict__ X,
                                                 const float* __restrict__ g,
                                                 const float* __restrict__ bta,
                                                 __nv_bfloat16* __restrict__ Y)
{
    const int warp = threadIdx.x >> 5, lane = threadIdx.x & 31;
    const int row = blockIdx.x * 8 + warp;
    const float* x = X + (size_t)row * DIM;

    float4 v[6];
    #pragma unroll
    for (int k = 0; k < 6; k++)
        v[k] = *(const float4*)(x + k * 128 + lane * 4);

    float s = 0.f, q = 0.f;
    #pragma unroll
    for (int k = 0; k < 6; k++) {
        s += v[k].x + v[k].y + v[k].z + v[k].w;
        q += v[k].x * v[k].x + v[k].y * v[k].y + v[k].z * v[k].z + v[k].w * v[k].w;
    }
    #pragma unroll
    for (int o = 16; o > 0; o >>= 1) {
        s += __shfl_xor_sync(0xffffffffu, s, o);
        q += __shfl_xor_sync(0xffffffffu, q, o);
    }
    const float m = s * (1.f / DIM);
    const float r = rsqrtf(q * (1.f / DIM) - m * m + 1e-6f);

    __nv_bfloat16* y = Y + (size_t)row * DIM;
    #pragma unroll
    for (int k = 0; k < 6; k++) {
        const int i = k * 128 + lane * 4;
        float4 g4 = *(const float4*)(g + i);
        float4 b4 = *(const float4*)(bta + i);
        float o0 = (v[k].x - m) * r * g4.x + b4.x;
        float o1 = (v[k].y - m) * r * g4.y + b4.y;
        float o2 = (v[k].z - m) * r * g4.z + b4.z;
        float o3 = (v[k].w - m) * r * g4.w + b4.w;
        __nv_bfloat162 h0, h1;
        h0.x = __float2bfloat16(o0); h0.y = __float2bfloat16(o1);
        h1.x = __float2bfloat16(o2); h1.y = __float2bfloat16(o3);
        uint2 pk;
        pk.x = *(uint32_t*)&h0; pk.y = *(uint32_t*)&h1;
        *(uint2*)(y + i) = pk;
    }
}

// ---------------- one-shot weight prep ----------------
#define SEG0 (DIM*DV)
#define SEG1 (DV*DIM)
#define SEG2 (DIM*HID)
#define SEG3 (HID*DIM)
#define SEG4 (OA_LD*DIM)
#define PREP_TOT (SEG0+SEG1+SEG2+SEG3+SEG4+OA_LD)
__global__ __launch_bounds__(256) void prep_weights(
    const float* __restrict__ W_val, const float* __restrict__ W_out,
    const float* __restrict__ fc1_w, const float* __restrict__ fc2_w,
    const float* __restrict__ Woff, const float* __restrict__ Wattn,
    const float* __restrict__ boff, const float* __restrict__ battn,
    __nv_bfloat16* __restrict__ wval, __nv_bfloat16* __restrict__ wout,
    __nv_bfloat16* __restrict__ wfc1, __nv_bfloat16* __restrict__ wfc2,
    __nv_bfloat16* __restrict__ wproj, float* __restrict__ bproj)
{
    int gid = blockIdx.x * 256 + threadIdx.x;
    if (gid < SEG0) {
        int k = gid / DV, n = gid % DV;
        wval[(size_t)n * DIM + k] = __float2bfloat16(W_val[gid]);
        return;
    }
    gid -= SEG0;
    if (gid < SEG1) {
        int k = gid / DIM, n = gid % DIM;
        wout[(size_t)n * DV + k] = __float2bfloat16(W_out[gid]);
        return;
    }
    gid -= SEG1;
    if (gid < SEG2) {
        int k = gid / HID, n = gid % HID;
        wfc1[(size_t)n * DIM + k] = __float2bfloat16(fc1_w[gid]);
        return;
    }
    gid -= SEG2;
    if (gid < SEG3) {
        int k = gid / DIM, n = gid % DIM;
        wfc2[(size_t)n * HID + k] = __float2bfloat16(fc2_w[gid]);
        return;
    }
    gid -= SEG3;
    if (gid < SEG4) {
        int n = gid / DIM, k = gid % DIM;
        float v = 0.f;
        if (n < 48)      v = Woff[(size_t)k * 48 + n];
        else if (n < 72) v = Wattn[(size_t)k * 24 + (n - 48)];
        wproj[gid] = __float2bfloat16(v);
        return;
    }
    gid -= SEG4;
    if (gid < OA_LD)
        bproj[gid] = (gid < 48) ? boff[gid] : ((gid < 72) ? battn[gid - 48] : 0.f);
}

// ---------------- bf16 mma.sync GEMM (R6-proven): BK=32, 2-stage --------
#define BM 128
#define BN 96
#define APAD 40
#define STG ((BM + BN) * APAD)
#define GEMM_SMEM (2 * STG * 2)

template<bool RES, bool ACC, bool OUTBF>
__global__ __launch_bounds__(256) void gemm_mma(
    const __nv_bfloat16* __restrict__ A,   // [M,K] row-major
    const __nv_bfloat16* __restrict__ Bt,  // [N,K] row-major
    const float* __restrict__ bias,        // [N]
    const float* __restrict__ R,           // [M,N] residual (RES)
    void* __restrict__ Cv, int M, int N, int K)
{
    extern __shared__ __nv_bfloat16 dsm[];

    const int tid  = threadIdx.x;
    const int wid  = tid >> 5, lane = tid & 31;
    const int wm   = wid >> 1, wn = wid & 1;
    const int bm   = blockIdx.y * BM, bn = blockIdx.x * BN;

    float acc[2][6][4];
    #pragma unroll
    for (int i = 0; i < 2; i++)
        #pragma unroll
        for (int j = 0; j < 6; j++)
            #pragma unroll
            for (int v = 0; v < 4; v++) acc[i][j][v] = 0.f;

    const uint32_t uS = smem_u32(dsm);
    const int ar0 = tid >> 2, ac0 = (tid & 3) * 8;
    const int ar1 = ar0 + 64;
    const int br0 = tid >> 2;
    const int br1 = br0 + 64;

    const int a_r = wm * 32 + (lane & 15);
    const int a_c = (lane >> 4) * 8;
    const int b_r = wn * 48 + ((lane >> 4) & 1) * 8 + (lane & 7);
    const int b_c = ((lane >> 3) & 1) * 8;

    const int nk = K >> 5;

    {
        const uint32_t baseA = uS;
        const uint32_t baseB = uS + (uint32_t)(BM * APAD) * 2;
        cp16(baseA + (uint32_t)(ar0 * APAD + ac0) * 2, A  + (size_t)(bm + ar0) * K + ac0);
        cp16(baseA + (uint32_t)(ar1 * APAD + ac0) * 2, A  + (size_t)(bm + ar1) * K + ac0);
        cp16(baseB + (uint32_t)(br0 * APAD + ac0) * 2, Bt + (size_t)(bn + br0) * K + ac0);
        if (tid < 128)
            cp16(baseB + (uint32_t)(br1 * APAD + ac0) * 2, Bt + (size_t)(bn + br1) * K + ac0);
        CP_COMMIT();
    }

    for (int c = 0; c < nk; c++) {
        CP_WAIT(0);
        __syncthreads();

        if (c + 1 < nk) {
            const int k0 = (c + 1) << 5;
            const uint32_t baseA = uS + (uint32_t)(((c + 1) & 1) * STG) * 2;
            const uint32_t baseB = baseA + (uint32_t)(BM * APAD) * 2;
            cp16(baseA + (uint32_t)(ar0 * APAD + ac0) * 2,
                 A + (size_t)(bm + ar0) * K + k0 + ac0);
            cp16(baseA + (uint32_t)(ar1 * APAD + ac0) * 2,
                 A + (size_t)(bm + ar1) * K + k0 + ac0);
            cp16(baseB + (uint32_t)(br0 * APAD + ac0) * 2,
                 Bt + (size_t)(bn + br0) * K + k0 + ac0);
            if (tid < 128)
                cp16(baseB + (uint32_t)(br1 * APAD + ac0) * 2,
                     Bt + (size_t)(bn + br1) * K + k0 + ac0);
            CP_COMMIT();
        }

        const uint32_t bA = uS + (uint32_t)((c & 1) * STG) * 2;
        const uint32_t bB = bA + (uint32_t)(BM * APAD) * 2;
        #pragma unroll
        for (int kk = 0; kk < 2; kk++) {
            uint32_t afr[2][4];
            #pragma unroll
            for (int mt = 0; mt < 2; mt++)
                ldmx4(afr[mt], bA + (uint32_t)((a_r + mt * 16) * APAD + kk * 16 + a_c) * 2);
            uint32_t bfr[6][2];
            #pragma unroll
            for (int g = 0; g < 3; g++) {
                uint32_t r[4];
                ldmx4(r, bB + (uint32_t)((b_r + g * 16) * APAD + kk * 16 + b_c) * 2);
                bfr[g * 2 + 0][0] = r[0]; bfr[g * 2 + 0][1] = r[1];
                bfr[g * 2 + 1][0] = r[2]; bfr[g * 2 + 1][1] = r[3];
            }
            #pragma unroll
            for (int mt = 0; mt < 2; mt++)
                #pragma unroll
                for (int nt = 0; nt < 6; nt++)
                    mma16816(acc[mt][nt], afr[mt], bfr[nt]);
        }
    }

    const int er = bm + wm * 32 + (lane >> 2);
    const int ec = bn + wn * 48 + (lane & 3) * 2;
    #pragma unroll
    for (int mt = 0; mt < 2; mt++) {
        #pragma unroll
        for (int nt = 0; nt < 6; nt++) {
            const int row0 = er + mt * 16;
            const int col  = ec + nt * 8;
            float2 bv = *(const float2*)&bias[col];
            size_t off0 = (size_t)row0 * N + col;
            size_t off1 = off0 + (size_t)8 * N;
            float2 o0, o1;
            o0.x = acc[mt][nt][0] + bv.x; o0.y = acc[mt][nt][1] + bv.y;
            o1.x = acc[mt][nt][2] + bv.x; o1.y = acc[mt][nt][3] + bv.y;
            if (OUTBF) {
                __nv_bfloat16* Cb = (__nv_bfloat16*)Cv;
                __nv_bfloat162 h0, h1;
                h0.x = __float2bfloat16(o0.x); h0.y = __float2bfloat16(o0.y);
                h1.x = __float2bfloat16(o1.x); h1.y = __float2bfloat16(o1.y);
                *(__nv_bfloat162*)&Cb[off0] = h0;
                *(__nv_bfloat162*)&Cb[off1] = h1;
            } else {
                float* C = (float*)Cv;
                if (RES) {
                    float2 r0 = *(const float2*)&R[off0];
                    float2 r1 = *(const float2*)&R[off1];
                    o0.x += r0.x; o0.y += r0.y; o1.x += r1.x; o1.y += r1.y;
                }
                if (ACC) {
                    float2 c0 = *(const float2*)&C[off0];
                    float2 c1 = *(const float2*)&C[off1];
                    o0.x += c0.x; o0.y += c0.y; o1.x += c1.x; o1.y += c1.y;
                }
                *(float2*)&C[off0] = o0;
                *(float2*)&C[off1] = o1;
            }
        }
    }
}

// ---------------- sampling: warp-per-token, 8 tokens per block ----------
__global__ __launch_bounds__(256) void sample_kernel(
    const float* __restrict__ oa,       // [NTOK, 96]  (absolute)
    const float* __restrict__ refp,
    __nv_bfloat16* __restrict__ attn_bf,
    int t0)
{
    __shared__ int   sidx[8][96];
    __shared__ float swt[8][96];

    const int wid = threadIdx.x >> 5, lane = threadIdx.x & 31;
    const int t = t0 + blockIdx.x * 8 + wid;
    const float* oarow = oa + (size_t)t * OA_LD;

    if (lane < 24) {
        const int h = lane >> 2, p = lane & 3;
        float l0 = oarow[48 + h * 4 + 0], l1 = oarow[48 + h * 4 + 1];
        float l2 = oarow[48 + h * 4 + 2], l3 = oarow[48 + h * 4 + 3];
        float mx = fmaxf(fmaxf(l0, l1), fmaxf(l2, l3));
        float e0 = expf(l0 - mx), e1 = expf(l1 - mx);
        float e2 = expf(l2 - mx), e3 = expf(l3 - mx);
        float inv = 1.f / (e0 + e1 + e2 + e3);
        float ep = (p == 0) ? e0 : (p == 1) ? e1 : (p == 2) ? e2 : e3;
        const float a = ep * inv;

        float rx = refp[(size_t)t * 2 + 0];
        float ry = refp[(size_t)t * 2 + 1];
        float lx = rx + oarow[h * 8 + p * 2 + 0] * (1.f / (float)WW);
        float ly = ry + oarow[h * 8 + p * 2 + 1] * (1.f / (float)HH);
        float x = lx * (float)WW - 0.5f;
        float y = ly * (float)HH - 0.5f;
        float x0f = floorf(x), y0f = floorf(y);
        float wx = x - x0f, wy = y - y0f;
        int x0 = (int)x0f, y0 = (int)y0f;
        #pragma unroll
        for (int c = 0; c < 4; c++) {
            int dx = c & 1, dy = c >> 1;
            int xi = x0 + dx, yi = y0 + dy;
            bool ok = (xi >= 0) && (xi < WW) && (yi >= 0) && (yi < HH);
            sidx[wid][lane * 4 + c] = ok ? (yi * WW + xi) : -1;
            float wgt = (dx ? wx : 1.f - wx) * (dy ? wy : 1.f - wy);
            swt[wid][lane * 4 + c] = ok ? wgt * a : 0.f;
        }
    }
    __syncwarp();

    const __nv_bfloat16* vb = g_v + (size_t)(t / LQ) * LIN * DV;
    #pragma unroll
    for (int j = 0; j < 6; j++) {            // head == j for this lane's dims
        const int d = j * 64 + lane * 2;
        float ax = 0.f, ay = 0.f;
        #pragma unroll
        for (int p = 0; p < 4; p++) {
            const int hp = j * 4 + p;
            #pragma unroll
            for (int c = 0; c < 4; c++) {
                int idx = sidx[wid][hp * 4 + c];
                float wv = swt[wid][hp * 4 + c];
                if (idx >= 0) {
                    __nv_bfloat162 v = *(const __nv_bfloat162*)&vb[(size_t)idx * DV + d];
                    ax += wv * __bfloat162float(v.x);
                    ay += wv * __bfloat162float(v.y);
                }
            }
        }
        __nv_bfloat162 o;
        o.x = __float2bfloat16(ax); o.y = __float2bfloat16(ay);
        *(__nv_bfloat162*)&attn_bf[(size_t)t * DV + d] = o;
    }
}

// ---------------- depthwise 3x3 conv (bf16 in) + GELU, 4 outs/thread ----
__global__ __launch_bounds__(256) void dwconv_gelu(
    const __nv_bfloat16* __restrict__ hin, const float* __restrict__ dww,
    const float* __restrict__ dwb, __nv_bfloat16* __restrict__ hout,
    int gid0)
{
    const int base = gid0 + blockIdx.x * 1024 + threadIdx.x;
    #pragma unroll
    for (int it = 0; it < 4; it++) {
        const int gid = base + it * 256;
        int ch = gid % HID;
        int t  = (gid / HID) % LQ;
        int b  = gid / (HID * LQ);

        int lvbase, hh, ww;
        if (t < 4096)      { lvbase = 0;    hh = 64; ww = 64; }
        else if (t < 5120) { lvbase = 4096; hh = 32; ww = 32; }
        else               { lvbase = 5120; hh = 16; ww = 16; }
        int tl = t - lvbase;
        int rr = tl / ww, cc = tl % ww;

        const __nv_bfloat16* in = hin + ((size_t)b * LQ + lvbase) * HID + ch;
        float acc = dwb[ch];
        #pragma unroll
        for (int ky = 0; ky < 3; ky++) {
            int y = rr + ky - 1;
            if (y < 0 || y >= hh) continue;
            #pragma unroll
            for (int kx = 0; kx < 3; kx++) {
                int x = cc + kx - 1;
                if (x < 0 || x >= ww) continue;
                acc += __bfloat162float(in[(size_t)(y * ww + x) * HID])
                     * dww[(ky * 3 + kx) * HID + ch];
            }
        }
        float ge = 0.5f * acc * (1.f + erff(acc * 0.70710678118654752440f));
        hout[gid] = __float2bfloat16(ge);
    }
}

// ---------------- host launcher ----------------
extern "C" void kernel_launch(void* const* d_in, const int* in_sizes, int n_in,
                              void* d_out, int out_size)
{
    const float* query  = (const float*)d_in[0];
    const float* refp   = (const float*)d_in[1];
    const float* feat   = (const float*)d_in[2];
    const float* qn_g   = (const float*)d_in[5];
    const float* qn_b   = (const float*)d_in[6];
    const float* fn_g   = (const float*)d_in[7];
    const float* fn_b   = (const float*)d_in[8];
    const float* W_off  = (const float*)d_in[9];
    const float* b_off  = (const float*)d_in[10];
    const float* W_attn = (const float*)d_in[11];
    const float* b_attn = (const float*)d_in[12];
    const float* W_val  = (const float*)d_in[13];
    const float* b_val  = (const float*)d_in[14];
    const float* W_out  = (const float*)d_in[15];
    const float* b_out  = (const float*)d_in[16];
    const float* ffn_g  = (const float*)d_in[17];
    const float* ffn_b  = (const float*)d_in[18];
    const float* fc1_w  = (const float*)d_in[19];
    const float* fc1_b  = (const float*)d_in[20];
    const float* dw_w   = (const float*)d_in[21];
    const float* dw_b   = (const float*)d_in[22];
    const float* fc2_w  = (const float*)d_in[23];
    const float* fc2_b  = (const float*)d_in[24];
    float* out = (float*)d_out;

    float *poa, *pbproj;
    __nv_bfloat16 *pv, *ph1b, *plnq, *plnf, *plnx, *pattnb, *ph2b;
    __nv_bfloat16 *pwval, *pwout, *pwproj, *pwfc1, *pwfc2;
    cudaGetSymbolAddress((void**)&pv,     g_v);
    cudaGetSymbolAddress((void**)&poa,    g_oa);
    cudaGetSymbolAddress((void**)&ph1b,   g_h1b);
    cudaGetSymbolAddress((void**)&pbproj, g_bproj);
    cudaGetSymbolAddress((void**)&plnq,   g_lnq);
    cudaGetSymbolAddress((void**)&plnf,   g_lnf);
    cudaGetSymbolAddress((void**)&plnx,   g_lnx);
    cudaGetSymbolAddress((void**)&pattnb, g_attnb);
    cudaGetSymbolAddress((void**)&ph2b,   g_h2b);
    cudaGetSymbolAddress((void**)&pwval,  g_wval);
    cudaGetSymbolAddress((void**)&pwout,  g_wout);
    cudaGetSymbolAddress((void**)&pwproj, g_wproj);
    cudaGetSymbolAddress((void**)&pwfc1,  g_wfc1);
    cudaGetSymbolAddress((void**)&pwfc2,  g_wfc2);

    cudaFuncSetAttribute(gemm_mma<false,false,true>,
        cudaFuncAttributeMaxDynamicSharedMemorySize, GEMM_SMEM);
    cudaFuncSetAttribute(gemm_mma<false,false,false>,
        cudaFuncAttributeMaxDynamicSharedMemorySize, GEMM_SMEM);
    cudaFuncSetAttribute(gemm_mma<true,false,false>,
        cudaFuncAttributeMaxDynamicSharedMemorySize, GEMM_SMEM);
    cudaFuncSetAttribute(gemm_mma<false,true,false>,
        cudaFuncAttributeMaxDynamicSharedMemorySize, GEMM_SMEM);

    const int GM = NQUAR / BM;     // 84 row-tiles per chunk
    cudaStream_t cs[NCHUNK] = {0, g_si.st[0], g_si.st[1], g_si.st[2]};

    // ---- main: weight prep (gates proj + v GEMMs) ----
    prep_weights<<<(PREP_TOT + 255) / 256, 256>>>(
        W_val, W_out, fc1_w, fc2_w, W_off, W_attn, b_off, b_attn,
        pwval, pwout, pwfc1, pwfc2, pwproj, pbproj);
    cudaEventRecord(g_si.e0, 0);

    // ---- sv: feat LN -> v GEMM ----
    ln_cast_w<<<NFEAT / 8, 256, 0, g_si.sv>>>(feat, fn_g, fn_b, plnf);
    cudaStreamWaitEvent(g_si.sv, g_si.e0, 0);
    gemm_mma<false, false, true><<<dim3(DV / BN, NFEAT / BM), 256, GEMM_SMEM, g_si.sv>>>(
        plnf, pwval, b_val, nullptr, pv, NFEAT, DV, DIM);
    cudaEventRecord(g_si.ev, g_si.sv);

    // ---- per-chunk pipelines (chunk c on stream cs[c]) ----
    // stage 1: ln_q
    for (int c = 0; c < NCHUNK; c++) {
        const size_t off = (size_t)c * NQUAR;
        ln_cast_w<<<NQUAR / 8, 256, 0, cs[c]>>>(
            query + off * DIM, qn_g, qn_b, plnq + off * DIM);
        if (c > 0) cudaStreamWaitEvent(cs[c], g_si.e0, 0);
    }
    // stage 2: proj GEMM
    for (int c = 0; c < NCHUNK; c++) {
        const size_t off = (size_t)c * NQUAR;
        gemm_mma<false, false, false><<<dim3(1, GM), 256, GEMM_SMEM, cs[c]>>>(
            plnq + off * DIM, pwproj, pbproj, nullptr,
            poa + off * OA_LD, NQUAR, OA_LD, DIM);
    }
    // stage 3: sample (needs v)
    for (int c = 0; c < NCHUNK; c++) {
        cudaStreamWaitEvent(cs[c], g_si.ev, 0);
        sample_kernel<<<NQUAR / 8, 256, 0, cs[c]>>>(poa, refp, pattnb,
                                                    c * NQUAR);
    }
    // stage 4: W_out GEMM (+query residual)
    for (int c = 0; c < NCHUNK; c++) {
        const size_t off = (size_t)c * NQUAR;
        gemm_mma<true, false, false><<<dim3(DIM / BN, GM), 256, GEMM_SMEM, cs[c]>>>(
            pattnb + off * DV, pwout, b_out, query + off * DIM,
            out + off * DIM, NQUAR, DIM, DV);
    }
    // stage 5: LN(x)
    for (int c = 0; c < NCHUNK; c++) {
        const size_t off = (size_t)c * NQUAR;
        ln_cast_w<<<NQUAR / 8, 256, 0, cs[c]>>>(
            out + off * DIM, ffn_g, ffn_b, plnx + off * DIM);
    }
    // stage 6: fc1
    for (int c = 0; c < NCHUNK; c++) {
        const size_t off = (size_t)c * NQUAR;
        gemm_mma<false, false, true><<<dim3(HID / BN, GM), 256, GEMM_SMEM, cs[c]>>>(
            plnx + off * DIM, pwfc1, fc1_b, nullptr,
            ph1b + off * HID, NQUAR, HID, DIM);
    }
    // stage 7: dwconv + gelu
    for (int c = 0; c < NCHUNK; c++) {
        dwconv_gelu<<<(NQUAR * HID) / 1024, 256, 0, cs[c]>>>(
            ph1b, dw_w, dw_b, ph2b, c * NQUAR * HID);
    }
    // stage 8: fc2 (+= into out)
    for (int c = 0; c < NCHUNK; c++) {
        const size_t off = (size_t)c * NQUAR;
        gemm_mma<false, true, false><<<dim3(DIM / BN, GM), 256, GEMM_SMEM, cs[c]>>>(
            ph2b + off * HID, pwfc2, fc2_b, nullptr,
            out + off * DIM, NQUAR, DIM, HID);
    }

    // join: default stream waits for chunks 1..3
    for (int c = 1; c < NCHUNK; c++) {
        cudaEventRecord(g_si.ej[c - 1], cs[c]);
        cudaStreamWaitEvent(0, g_si.ej[c - 1], 0);
    }
}